// round 13
// baseline (speedup 1.0000x reference)
#include <cuda_runtime.h>
#include <math.h>

#define B_ 4
#define C_ 32
#define L_ 256
#define M_ 256
#define F_ 8
#define N_ 64
#define CL_ (L_ * M_)              // c-stride in x (elements)
#define BLKL_ 4                    // l's per CTA
#define THREADS_ 512
#define STG_ 3                     // ring slots
#define CPS_ 4                     // c's per stage
#define NSG_ (C_ / CPS_)           // 8 stages
#define CBYTES_ (BLKL_ * M_ * 4)   // 4096: one (c, tensor) slice
#define STGB_ (CPS_ * 2 * CBYTES_) // 32768 per stage
#define XS_BYTES (STG_ * STGB_)    // 98304
#define W_OFF   XS_BYTES
#define W_BYTES (BLKL_ * C_ * F_ * 16)   // 16384
#define MB_OFF  (W_OFF + W_BYTES)        // 114688
#define SMEM_TOTAL (MB_OFF + STG_ * 8)   // 114712 -> 2 CTAs/SM

typedef unsigned long long u64;

__device__ __forceinline__ u64 ffma2(u64 a, u64 b, u64 c) {
    u64 d;
    asm("fma.rn.f32x2 %0, %1, %2, %3;" : "=l"(d) : "l"(a), "l"(b), "l"(c));
    return d;
}
__device__ __forceinline__ void upk(u64 v, float& x, float& y) {
    asm("mov.b64 {%0, %1}, %2;" : "=f"(x), "=f"(y) : "l"(v));
}
__device__ __forceinline__ u64 neg2(u64 v) {
    u64 d;
    asm("{\n\t"
        ".reg .b32 lo, hi;\n\t"
        "mov.b64 {lo, hi}, %1;\n\t"
        "xor.b32 lo, lo, 0x80000000;\n\t"
        "xor.b32 hi, hi, 0x80000000;\n\t"
        "mov.b64 %0, {lo, hi};\n\t"
        "}" : "=l"(d) : "l"(v));
    return d;
}
// 4KB bulk copy global->shared, completion counted on mbarrier.
__device__ __forceinline__ void bulk4k(unsigned int sdst, const void* gsrc,
                                       unsigned int mbar) {
    asm volatile(
        "cp.async.bulk.shared::cta.global.mbarrier::complete_tx::bytes "
        "[%0], [%1], 4096, [%2];"
        :: "r"(sdst), "l"(gsrc), "r"(mbar) : "memory");
}
// Wait for completion of phase `parity` (runtime value).
__device__ __forceinline__ void mbar_wait(unsigned int mbar, unsigned parity) {
    asm volatile(
        "{\n\t"
        ".reg .pred P1;\n\t"
        "WAIT_%=:\n\t"
        "mbarrier.try_wait.parity.acquire.cta.shared::cta.b64 P1, [%0], %1, 0x989680;\n\t"
        "@P1 bra.uni DONE_%=;\n\t"
        "bra.uni WAIT_%=;\n\t"
        "DONE_%=:\n\t"
        "}" :: "r"(mbar), "r"(parity) : "memory");
}

__global__ __launch_bounds__(THREADS_, 2) void sphere_conv_kernel(
    const float* __restrict__ xr, const float* __restrict__ xi,
    const float* __restrict__ wr, const float* __restrict__ wi,
    float* __restrict__ out)
{
    extern __shared__ char smem[];
    float4* w4s = (float4*)(smem + W_OFF);

    const unsigned int sx  = (unsigned int)__cvta_generic_to_shared(smem);
    const unsigned int smb = sx + MB_OFF;

    const int tid  = threadIdx.x;
    const int mp   = tid & 127;          // m-pair: m = 2*mp, 2*mp+1
    const int lsel = tid >> 7;           // 0..3: l within block
    const int b    = blockIdx.x >> 6;    // 4 b x 64 l-blocks
    const int lblk = blockIdx.x & 63;
    const int l    = lblk * BLKL_ + lsel;

    if (tid == 0) {
#pragma unroll
        for (int s = 0; s < STG_; ++s)
            asm volatile("mbarrier.init.shared.b64 [%0], 1;"
                         :: "r"(smb + s * 8) : "memory");
    }

    // ---- interpolated weights: 4 l-sets of {wr,wr,wi,wi} per (f,c) ----
    for (int i = tid; i < BLKL_ * C_ * F_; i += THREADS_) {
        const int g   = i >> 8;          // which l-set
        const int idx = i & 255;
        const int f   = idx & (F_ - 1);
        const int c   = idx >> 3;
        const int lg  = lblk * BLKL_ + g;
        const float t = (float)(lg * (N_ - 1)) * (1.0f / (float)(L_ - 1));
        int lo = (int)t;
        if (lo > N_ - 2) lo = N_ - 2;
        const float frac = t - (float)lo;
        const float om   = 1.0f - frac;
        const int wix = (f * C_ + c) * N_ + lo;      // w layout (F,C,N,1)
        const float wrv = wr[wix] * om + wr[wix + 1] * frac;
        const float wiv = wi[wix] * om + wi[wix + 1] * frac;
        w4s[g * (C_ * F_) + c * F_ + f] = make_float4(wrv, wrv, wiv, wiv);
    }
    __syncthreads();   // mbars + weights visible

    // ---- producer: tid0 fills ring with 4KB bulk copies ----
    // INVARIANT (the R12 deadlock fix): stage s ALWAYS lives in slot s % STG_.
    const char* xrg = (const char*)(xr + (size_t)b * (C_ * CL_) + lblk * BLKL_ * M_);
    const char* xig = (const char*)(xi + (size_t)b * (C_ * CL_) + lblk * BLKL_ * M_);
    if (tid == 0) {
#pragma unroll
        for (int s = 0; s < STG_ - 1; ++s) {       // prologue: stages 0,1
            const unsigned int mb = smb + s * 8;
            asm volatile("mbarrier.arrive.expect_tx.shared.b64 _, [%0], %1;"
                         :: "r"(mb), "r"((unsigned)STGB_) : "memory");
#pragma unroll
            for (int j = 0; j < CPS_; ++j) {
                const size_t coff = (size_t)(s * CPS_ + j) * (CL_ * 4);
                const unsigned int sd = sx + s * STGB_ + j * (2 * CBYTES_);
                bulk4k(sd,            xrg + coff, mb);
                bulk4k(sd + CBYTES_,  xig + coff, mb);
            }
        }
    }

    u64 pr[F_], pi[F_];
#pragma unroll
    for (int f = 0; f < F_; ++f) { pr[f] = 0ull; pi[f] = 0ull; }

    // consumer smem bases for this thread
    const unsigned int xbase = sx + (unsigned)(lsel * 1024 + mp * 8);
    unsigned int soff = sx + W_OFF + (unsigned)(lsel * 4096);

#pragma unroll 1
    for (int sg = 0; sg < NSG_; ++sg) {
        const int slot = sg % STG_;
        mbar_wait(smb + slot * 8, (unsigned)((sg / STG_) & 1));
        const unsigned int st = xbase + (unsigned)(slot * STGB_);
#pragma unroll
        for (int j = 0; j < CPS_; ++j) {
            u64 x_r, x_i;
            asm("ld.shared.b64 %0, [%1];" : "=l"(x_r)
                : "r"(st + (unsigned)(j * 2 * CBYTES_)));
            asm("ld.shared.b64 %0, [%1];" : "=l"(x_i)
                : "r"(st + (unsigned)(j * 2 * CBYTES_ + CBYTES_)));
            const u64 nxi = neg2(x_i);
#pragma unroll
            for (int f = 0; f < F_; ++f) {
                u64 wrr, wii;
                asm("ld.shared.v2.u64 {%0, %1}, [%2];"
                    : "=l"(wrr), "=l"(wii)
                    : "r"(soff + (unsigned)(f * 16)));
                pr[f] = ffma2(wrr, x_r, pr[f]);   // + wr*xr
                pr[f] = ffma2(wii, nxi, pr[f]);   // - wi*xi
                pi[f] = ffma2(wii, x_r, pi[f]);   // + wi*xr
                pi[f] = ffma2(wrr, x_i, pi[f]);   // + wr*xi
            }
            soff += F_ * 16;                      // next c (sequential)
        }
        __syncthreads();       // slot fully consumed CTA-wide
        if (tid == 0 && sg < NSG_ - (STG_ - 1)) {
            const int s = sg + STG_ - 1;          // next stage to fetch
            const int wslot = s % STG_;           // == (sg+2)%3, freed at sg-1
            const unsigned int mb = smb + wslot * 8;
            asm volatile("mbarrier.arrive.expect_tx.shared.b64 _, [%0], %1;"
                         :: "r"(mb), "r"((unsigned)STGB_) : "memory");
#pragma unroll
            for (int j = 0; j < CPS_; ++j) {
                const size_t coff = (size_t)(s * CPS_ + j) * (CL_ * 4);
                const unsigned int sd = sx + wslot * STGB_ + j * (2 * CBYTES_);
                bulk4k(sd,           xrg + coff, mb);
                bulk4k(sd + CBYTES_, xig + coff, mb);
            }
        }
    }

    // ---- epilogue: scale = sqrt(1+l)/C, relu on real only ----
    const float s  = sqrtf(1.0f + (float)l) * (1.0f / (float)C_);
    float2* outp   = (float2*)out;
    const int ob   = (b * F_ * L_ + l) * M_ + 2 * mp;
#pragma unroll
    for (int f = 0; f < F_; ++f) {
        float r0, r1, i0, i1;
        upk(pr[f], r0, r1);
        upk(pi[f], i0, i1);
        const int idx = ob + f * (L_ * M_);
        outp[idx >> 1] = make_float2(fmaxf(r0 * s, 0.0f), fmaxf(r1 * s, 0.0f));
        outp[(idx + B_ * F_ * L_ * M_) >> 1] = make_float2(i0 * s, i1 * s);
    }
}

extern "C" void kernel_launch(void* const* d_in, const int* in_sizes, int n_in,
                              void* d_out, int out_size) {
    (void)in_sizes; (void)n_in; (void)out_size;
    cudaFuncSetAttribute(sphere_conv_kernel,
                         cudaFuncAttributeMaxDynamicSharedMemorySize, SMEM_TOTAL);
    sphere_conv_kernel<<<B_ * (L_ / BLKL_), THREADS_, SMEM_TOTAL>>>(
        (const float*)d_in[0], (const float*)d_in[1],
        (const float*)d_in[2], (const float*)d_in[3],
        (float*)d_out);
}

// round 14
// speedup vs baseline: 1.1631x; 1.1631x over previous
#include <cuda_runtime.h>
#include <math.h>

#define B_ 4
#define C_ 32
#define L_ 256
#define M_ 256
#define F_ 8
#define N_ 64
#define CL_ (L_ * M_)              // c-stride in x (elements)
#define BLKL_ 2                    // l's per CTA (contiguous pair)
#define THREADS_ 128
#define STG_ 3                     // ring slots
#define CPS_ 4                     // c's per stage
#define NSG_ (C_ / CPS_)           // 8 stages
#define CBYTES_ (BLKL_ * M_ * 4)   // 2048: one (c, tensor) slice (both l's)
#define STGB_ (CPS_ * 2 * CBYTES_) // 16384 per stage
#define XS_BYTES (STG_ * STGB_)    // 49152
#define W_OFF   XS_BYTES
#define W_BYTES (BLKL_ * C_ * F_ * 8)    // 4096 (float2 per (l,c,f))
#define MB_OFF  (W_OFF + W_BYTES)        // 53248
#define SMEM_TOTAL (MB_OFF + STG_ * 8)   // 53272 -> 4 CTAs/SM

typedef unsigned long long u64;

__device__ __forceinline__ u64 ffma2(u64 a, u64 b, u64 c) {
    u64 d;
    asm("fma.rn.f32x2 %0, %1, %2, %3;" : "=l"(d) : "l"(a), "l"(b), "l"(c));
    return d;
}
__device__ __forceinline__ void upk(u64 v, float& x, float& y) {
    asm("mov.b64 {%0, %1}, %2;" : "=f"(x), "=f"(y) : "l"(v));
}
__device__ __forceinline__ u64 neg2(u64 v) {
    u64 d;
    asm("{\n\t"
        ".reg .b32 lo, hi;\n\t"
        "mov.b64 {lo, hi}, %1;\n\t"
        "xor.b32 lo, lo, 0x80000000;\n\t"
        "xor.b32 hi, hi, 0x80000000;\n\t"
        "mov.b64 %0, {lo, hi};\n\t"
        "}" : "=l"(d) : "l"(v));
    return d;
}
// 2KB bulk copy global->shared, completion counted on mbarrier.
__device__ __forceinline__ void bulk2k(unsigned int sdst, const void* gsrc,
                                       unsigned int mbar) {
    asm volatile(
        "cp.async.bulk.shared::cta.global.mbarrier::complete_tx::bytes "
        "[%0], [%1], 2048, [%2];"
        :: "r"(sdst), "l"(gsrc), "r"(mbar) : "memory");
}
__device__ __forceinline__ void mbar_wait(unsigned int mbar, unsigned parity) {
    asm volatile(
        "{\n\t"
        ".reg .pred P1;\n\t"
        "WAIT_%=:\n\t"
        "mbarrier.try_wait.parity.acquire.cta.shared::cta.b64 P1, [%0], %1, 0x989680;\n\t"
        "@P1 bra.uni DONE_%=;\n\t"
        "bra.uni WAIT_%=;\n\t"
        "DONE_%=:\n\t"
        "}" :: "r"(mbar), "r"(parity) : "memory");
}

__global__ __launch_bounds__(THREADS_, 4) void sphere_conv_kernel(
    const float* __restrict__ xr, const float* __restrict__ xi,
    const float* __restrict__ wr, const float* __restrict__ wi,
    float* __restrict__ out)
{
    extern __shared__ char smem[];
    float2* w2s = (float2*)(smem + W_OFF);

    const unsigned int sx  = (unsigned int)__cvta_generic_to_shared(smem);
    const unsigned int smb = sx + MB_OFF;

    const int tid   = threadIdx.x;
    const int wid   = tid >> 5;
    const int lane  = tid & 31;
    const int lsel  = wid >> 1;          // 0/1: which l of the pair (warp-uniform)
    const int mloc  = ((wid & 1) << 5) + lane;   // 0..63; m = 4*mloc
    const int b     = blockIdx.x >> 7;   // 4 b x 128 l-pairs
    const int lp    = blockIdx.x & 127;
    const int l     = lp * BLKL_ + lsel;

    if (tid == 0) {
#pragma unroll
        for (int s = 0; s < STG_; ++s)
            asm volatile("mbarrier.init.shared.b64 [%0], 1;"
                         :: "r"(smb + s * 8) : "memory");
    }

    // ---- interpolated weights: 2 l-sets of {wr, wi} per (c,f) ----
    for (int i = tid; i < BLKL_ * C_ * F_; i += THREADS_) {
        const int g   = i >> 8;          // which l-set
        const int idx = i & 255;
        const int f   = idx & (F_ - 1);
        const int c   = idx >> 3;
        const int lg  = lp * BLKL_ + g;
        const float t = (float)(lg * (N_ - 1)) * (1.0f / (float)(L_ - 1));
        int lo = (int)t;
        if (lo > N_ - 2) lo = N_ - 2;
        const float frac = t - (float)lo;
        const float om   = 1.0f - frac;
        const int wix = (f * C_ + c) * N_ + lo;      // w layout (F,C,N,1)
        w2s[g * (C_ * F_) + c * F_ + f] =
            make_float2(wr[wix] * om + wr[wix + 1] * frac,
                        wi[wix] * om + wi[wix + 1] * frac);
    }
    __syncthreads();   // mbars + weights visible

    // ---- producer: tid0 fills ring with 2KB bulk copies ----
    // INVARIANT: stage s ALWAYS lives in slot s % STG_.
    const char* xrg = (const char*)(xr + (size_t)b * (C_ * CL_) + lp * BLKL_ * M_);
    const char* xig = (const char*)(xi + (size_t)b * (C_ * CL_) + lp * BLKL_ * M_);
    if (tid == 0) {
#pragma unroll
        for (int s = 0; s < STG_ - 1; ++s) {       // prologue: stages 0,1
            const unsigned int mb = smb + s * 8;
            asm volatile("mbarrier.arrive.expect_tx.shared.b64 _, [%0], %1;"
                         :: "r"(mb), "r"((unsigned)STGB_) : "memory");
#pragma unroll
            for (int j = 0; j < CPS_; ++j) {
                const size_t coff = (size_t)(s * CPS_ + j) * (CL_ * 4);
                const unsigned int sd = sx + s * STGB_ + j * (2 * CBYTES_);
                bulk2k(sd,            xrg + coff, mb);
                bulk2k(sd + CBYTES_,  xig + coff, mb);
            }
        }
    }

    // accumulators: 8 f x {pr,pi} x 2 m-pairs
    u64 pr[F_][2], pi[F_][2];
#pragma unroll
    for (int f = 0; f < F_; ++f) {
        pr[f][0] = pr[f][1] = 0ull;
        pi[f][0] = pi[f][1] = 0ull;
    }

    const unsigned int xtoff = (unsigned)(lsel * 1024 + mloc * 16);
    unsigned int soff = sx + W_OFF + (unsigned)(lsel * (C_ * F_ * 8));

#pragma unroll 1
    for (int sg = 0; sg < NSG_; ++sg) {
        const int slot = sg % STG_;
        mbar_wait(smb + slot * 8, (unsigned)((sg / STG_) & 1));
        const unsigned int st = sx + (unsigned)(slot * STGB_) + xtoff;
#pragma unroll
        for (int j = 0; j < CPS_; ++j) {
            u64 xr0, xr1, xi0, xi1;
            asm("ld.shared.v2.u64 {%0, %1}, [%2];" : "=l"(xr0), "=l"(xr1)
                : "r"(st + (unsigned)(j * 2 * CBYTES_)));
            asm("ld.shared.v2.u64 {%0, %1}, [%2];" : "=l"(xi0), "=l"(xi1)
                : "r"(st + (unsigned)(j * 2 * CBYTES_ + CBYTES_)));
            const u64 ni0 = neg2(xi0), ni1 = neg2(xi1);
#pragma unroll
            for (int f = 0; f < F_; ++f) {
                unsigned int wrv, wiv;
                asm("ld.shared.v2.b32 {%0, %1}, [%2];"
                    : "=r"(wrv), "=r"(wiv)
                    : "r"(soff + (unsigned)(f * 8)));
                u64 wrr, wii;
                asm("mov.b64 %0, {%1, %1};" : "=l"(wrr) : "r"(wrv));
                asm("mov.b64 %0, {%1, %1};" : "=l"(wii) : "r"(wiv));
                pr[f][0] = ffma2(wrr, xr0, pr[f][0]);
                pr[f][1] = ffma2(wrr, xr1, pr[f][1]);
                pr[f][0] = ffma2(wii, ni0, pr[f][0]);
                pr[f][1] = ffma2(wii, ni1, pr[f][1]);
                pi[f][0] = ffma2(wii, xr0, pi[f][0]);
                pi[f][1] = ffma2(wii, xr1, pi[f][1]);
                pi[f][0] = ffma2(wrr, xi0, pi[f][0]);
                pi[f][1] = ffma2(wrr, xi1, pi[f][1]);
            }
            soff += F_ * 8;                       // next c (sequential)
        }
        __syncthreads();       // slot fully consumed CTA-wide
        if (tid == 0 && sg < NSG_ - (STG_ - 1)) {
            const int s = sg + STG_ - 1;          // next stage to fetch
            const int wslot = s % STG_;           // freed at iteration sg-1
            const unsigned int mb = smb + wslot * 8;
            asm volatile("mbarrier.arrive.expect_tx.shared.b64 _, [%0], %1;"
                         :: "r"(mb), "r"((unsigned)STGB_) : "memory");
#pragma unroll
            for (int j = 0; j < CPS_; ++j) {
                const size_t coff = (size_t)(s * CPS_ + j) * (CL_ * 4);
                const unsigned int sd = sx + wslot * STGB_ + j * (2 * CBYTES_);
                bulk2k(sd,           xrg + coff, mb);
                bulk2k(sd + CBYTES_, xig + coff, mb);
            }
        }
    }

    // ---- epilogue: scale = sqrt(1+l)/C, relu on real only ----
    const float s  = sqrtf(1.0f + (float)l) * (1.0f / (float)C_);
    const int  m0  = 4 * mloc;
    float4* outp   = (float4*)out;
    const int ob   = (b * F_ * L_ + l) * M_ + m0;
#pragma unroll
    for (int f = 0; f < F_; ++f) {
        float r0, r1, r2, r3, i0, i1, i2, i3;
        upk(pr[f][0], r0, r1); upk(pr[f][1], r2, r3);
        upk(pi[f][0], i0, i1); upk(pi[f][1], i2, i3);
        const int idx = ob + f * (L_ * M_);
        outp[idx >> 2] = make_float4(fmaxf(r0 * s, 0.0f), fmaxf(r1 * s, 0.0f),
                                     fmaxf(r2 * s, 0.0f), fmaxf(r3 * s, 0.0f));
        outp[(idx + B_ * F_ * L_ * M_) >> 2] =
            make_float4(i0 * s, i1 * s, i2 * s, i3 * s);
    }
}

extern "C" void kernel_launch(void* const* d_in, const int* in_sizes, int n_in,
                              void* d_out, int out_size) {
    (void)in_sizes; (void)n_in; (void)out_size;
    cudaFuncSetAttribute(sphere_conv_kernel,
                         cudaFuncAttributeMaxDynamicSharedMemorySize, SMEM_TOTAL);
    sphere_conv_kernel<<<B_ * (L_ / BLKL_), THREADS_, SMEM_TOTAL>>>(
        (const float*)d_in[0], (const float*)d_in[1],
        (const float*)d_in[2], (const float*)d_in[3],
        (float*)d_out);
}